// round 8
// baseline (speedup 1.0000x reference)
#include <cuda_runtime.h>
#include <cuda_bf16.h>
#include <cstdint>

#define BB 256
#define TT 512
#define NS 256
#define START_TAG 254
#define STOP_TAG 255
#define LN2F 0.6931471805599453f
#define NB 8
#define NCTA (BB / NB)
#define RSB 528           // ea row stride bytes (132 words -> conflict-free)
#define EABUF (NB * RSB)  // 4224

// scratch (allocation-free rule: __device__ globals)
__device__ float g_den[BB];
__device__ float g_num[BB];
// E = exp(trans) bf16, columns PRE-PERMUTED: g_Ebf[r*256+x] = exp(trans[r][perm(x)])
// perm(x) = 16*(x>>4) + ((x>>1)&7) + 8*(x&1)
__device__ unsigned short g_Ebf[NS * NS];

__device__ __forceinline__ int permf(int x) {
    return 16 * (x >> 4) + ((x >> 1) & 7) + 8 * (x & 1);
}
__device__ __forceinline__ int iperm(int s) {
    return 16 * (s >> 4) + 2 * (s & 7) + ((s >> 3) & 1);
}

// ---------------------------------------------------------------------------
// smem layout (static, ~10.7 KB)
// ---------------------------------------------------------------------------
#define SM_EA    0        // 2 x 4224 ea double buffer: [n][x] bf16 (permuted states)
#define SM_MSLOT 8448     // 2 x 8 floats (state-0 value per batch, renorm probe)
#define SM_MASK  8512     // 512 u32 mask bitfields
#define SM_C0    10560    // 8 floats
#define SM_RED   10592    // 64 floats
#define SM_KS    10848    // 8 ints
#define SM_SS    10880    // 8 floats
#define SM_TOTAL 10912

#define MMA_BF16(d, a, b0, b1) \
    asm volatile( \
        "mma.sync.aligned.m16n8k16.row.col.f32.bf16.bf16.f32 " \
        "{%0,%1,%2,%3},{%4,%5,%6,%7},{%8,%9},{%0,%1,%2,%3};" \
        : "+f"((d)[0]), "+f"((d)[1]), "+f"((d)[2]), "+f"((d)[3]) \
        : "r"((a)[0]), "r"((a)[1]), "r"((a)[2]), "r"((a)[3]), "r"(b0), "r"(b1))

// ---------------------------------------------------------------------------
// Prep: permuted bf16 E
// ---------------------------------------------------------------------------
__global__ void prep_kernel(const float* __restrict__ trans) {
    int gid = blockIdx.x * blockDim.x + threadIdx.x;  // 0..65535
    int r = gid >> 8, x = gid & 255;
    g_Ebf[gid] = __bfloat16_as_ushort(__float2bfloat16(__expf(trans[r * NS + permf(x)])));
}

// ---------------------------------------------------------------------------
// Forward recursion via mma.sync bf16: 16 warps, 1 m16 tile per warp.
// Linear space + stale state-0 power-of-2 renorm (exact via ksum).
// ---------------------------------------------------------------------------
__global__ void __launch_bounds__(512, 1) forward_kernel(
    const float* __restrict__ inputs,
    const float* __restrict__ trans,
    const int* __restrict__ mask)
{
    __shared__ __align__(16) char smem[SM_TOTAL];
    const uint32_t smem_base = (uint32_t)__cvta_generic_to_shared(smem);
    float*    mslotF = (float*)(smem + SM_MSLOT);
    uint32_t* masksS = (uint32_t*)(smem + SM_MASK);
    float*    C0sm   = (float*)(smem + SM_C0);
    float*    redsm  = (float*)(smem + SM_RED);
    int*      kssm   = (int*)(smem + SM_KS);
    float*    Ssm    = (float*)(smem + SM_SS);

    const int tid  = threadIdx.x;
    const int lane = tid & 31;
    const int wid  = tid >> 5;
    const int gidr = lane >> 2;   // groupID 0..7
    const int tig  = lane & 3;    // thread-in-group 0..3
    const int wbase = wid * 16;   // warp's 16-state tile base
    const int bb    = blockIdx.x * NB;
    const int n0 = 2 * tig, n1 = n0 + 1;

    // mask bitfields
    for (int tt = tid; tt < TT; tt += 512) {
        uint32_t w = 0;
#pragma unroll
        for (int n = 0; n < NB; n++) w |= (mask[(bb + n) * TT + tt] ? 1u : 0u) << n;
        masksS[tt] = w;
    }

    // A fragments from permuted E (64 u32/thread, resident)
    uint32_t A[16][4];
    {
        int r0 = wbase + gidr, r1 = r0 + 8;
#pragma unroll
        for (int kt = 0; kt < 16; kt++) {
            int c0 = kt * 16 + tig * 2;
            A[kt][0] = *(const uint32_t*)&g_Ebf[r0 * NS + c0];
            A[kt][1] = *(const uint32_t*)&g_Ebf[r1 * NS + c0];
            A[kt][2] = *(const uint32_t*)&g_Ebf[r0 * NS + c0 + 8];
            A[kt][3] = *(const uint32_t*)&g_Ebf[r1 * NS + c0 + 8];
        }
    }

    // alpha0: per-batch max -> C0; ea0 at physical iperm(state) (threads 0..255)
    {
        float a0v[NB];
        if (wid < 8) {
            float tS = trans[tid * NS + START_TAG];
#pragma unroll
            for (int n = 0; n < NB; n++)
                a0v[n] = tS + inputs[((size_t)(bb + n) * TT) * NS + tid];
#pragma unroll
            for (int n = 0; n < NB; n++) {
                float m = a0v[n];
#pragma unroll
                for (int o = 16; o; o >>= 1) m = fmaxf(m, __shfl_xor_sync(~0u, m, o));
                if (lane == 0) redsm[wid * 8 + n] = m;
            }
        }
        __syncthreads();
        if (tid < 8) {
            float m = -INFINITY;
#pragma unroll
            for (int w = 0; w < 8; w++) m = fmaxf(m, redsm[w * 8 + tid]);
            C0sm[tid] = m;
        }
        __syncthreads();
        if (wid < 8) {
            int xph = iperm(tid);
#pragma unroll
            for (int n = 0; n < NB; n++) {
                float e = __expf(a0v[n] - C0sm[n]);
                unsigned short h = __bfloat16_as_ushort(__float2bfloat16(e));
                uint32_t ad = smem_base + SM_EA + (uint32_t)(n * RSB + xph * 2);
                asm volatile("st.shared.b16 [%0], %1;" :: "r"(ad), "h"(h));
                if (tid == 0) mslotF[n] = e;
            }
        }
        __syncthreads();
    }

    // emission pointers: this thread's 2 states (r0, r1) x 2 batches (n0, n1)
    const float* pn0 = inputs + (size_t)(bb + n0) * TT * NS;
    const float* pn1 = inputs + (size_t)(bb + n1) * TT * NS;
    const int r0s = wbase + gidr, r1s = r0s + 8;

    float emA[4], emB[4];
    {
        const float* q0 = pn0 + (size_t)1 * NS;
        const float* q1 = pn1 + (size_t)1 * NS;
        emA[0] = q0[r0s]; emA[1] = q1[r0s]; emA[2] = q0[r1s]; emA[3] = q1[r1s];
    }
    {
        const float* q0 = pn0 + (size_t)2 * NS;
        const float* q1 = pn1 + (size_t)2 * NS;
        emB[0] = q0[r0s]; emB[1] = q1[r0s]; emB[2] = q0[r1s]; emB[3] = q1[r1s];
    }

    int ksum0 = 0, ksum1 = 0;
    uint32_t cur = 0;
    // epilogue store: one bf16x2 word per batch at phys word (8*wid + gidr)
    const uint32_t stoff = (uint32_t)((wbase + 2 * gidr) * 2);

    for (int t = 1; t < TT; t++) {
        const uint32_t bufb = smem_base + SM_EA + cur * EABUF;

        // hoisted: renorm, mask, exp(em) (independent of D)
        float ms0 = mslotF[cur * 8 + n0];
        float ms1 = mslotF[cur * 8 + n1];
        uint32_t mw = masksS[t - 1];
        uint32_t e0b = (__float_as_uint(ms0) >> 23) & 0xFFu;
        uint32_t e1b = (__float_as_uint(ms1) >> 23) & 0xFFu;
        ksum0 += (int)e0b - 127;
        ksum1 += (int)e1b - 127;
        float invM0 = __uint_as_float((254u - e0b) << 23);
        float invM1 = __uint_as_float((254u - e1b) << 23);
        float es[4];
        es[0] = __expf(emA[0]) * invM0;
        es[1] = __expf(emA[1]) * invM1;
        es[2] = __expf(emA[2]) * invM0;
        es[3] = __expf(emA[3]) * invM1;
#pragma unroll
        for (int i = 0; i < 4; i++) emA[i] = emB[i];
        if (t + 2 < TT) {
            const float* q0 = pn0 + (size_t)(t + 2) * NS;
            const float* q1 = pn1 + (size_t)(t + 2) * NS;
            emB[0] = q0[r0s]; emB[1] = q1[r0s]; emB[2] = q0[r1s]; emB[3] = q1[r1s];
        }

        // MMA: 16 HMMA in 4 independent chains (kt mod 4)
        float dA[4] = {0.f, 0.f, 0.f, 0.f}, dBc[4] = {0.f, 0.f, 0.f, 0.f};
        float dC[4] = {0.f, 0.f, 0.f, 0.f}, dD[4] = {0.f, 0.f, 0.f, 0.f};
        const uint32_t bbase = bufb + (uint32_t)(gidr * RSB + tig * 4);
#pragma unroll
        for (int half = 0; half < 2; half++) {
            uint32_t Bw[16];
#pragma unroll
            for (int k = 0; k < 8; k++) {
                uint32_t ad = bbase + (uint32_t)((half * 8 + k) * 32);
                asm volatile("ld.shared.b32 %0,[%1];" : "=r"(Bw[2 * k]) : "r"(ad));
                asm volatile("ld.shared.b32 %0,[%1];" : "=r"(Bw[2 * k + 1]) : "r"(ad + 16));
            }
#pragma unroll
            for (int k = 0; k < 8; k++) {
                int kt = half * 8 + k;
                switch (k & 3) {
                    case 0: MMA_BF16(dA, A[kt], Bw[2 * k], Bw[2 * k + 1]); break;
                    case 1: MMA_BF16(dBc, A[kt], Bw[2 * k], Bw[2 * k + 1]); break;
                    case 2: MMA_BF16(dC, A[kt], Bw[2 * k], Bw[2 * k + 1]); break;
                    default: MMA_BF16(dD, A[kt], Bw[2 * k], Bw[2 * k + 1]); break;
                }
            }
        }

        // rare masked path: per-batch sums of current ea
        float Sv0 = 0.f, Sv1 = 0.f;
        if (mw != 0xFFu) {
            if (wid < 8) {
                float s = 0.f;
#pragma unroll
                for (int q = 0; q < 4; q++) {
                    uint32_t v;
                    uint32_t ad = bufb + (uint32_t)(wid * RSB + (lane * 4 + q) * 4);
                    asm volatile("ld.shared.b32 %0,[%1];" : "=r"(v) : "r"(ad));
                    s += __uint_as_float(v << 16) + __uint_as_float(v & 0xFFFF0000u);
                }
#pragma unroll
                for (int o = 16; o; o >>= 1) s += __shfl_xor_sync(~0u, s, o);
                if (lane == 0) Ssm[wid] = s;
            }
            __syncthreads();
            Sv0 = Ssm[n0] * invM0;
            Sv1 = Ssm[n1] * invM1;
        }

        // epilogue: u = d*es, pack (r0,r1) bf16x2, 2x STS.32
        const uint32_t nxtb = smem_base + SM_EA + (cur ^ 1u) * EABUF;
        float u0 = (dA[0] + dBc[0] + dC[0] + dD[0]) * es[0];  // r0, n0
        float u1 = (dA[1] + dBc[1] + dC[1] + dD[1]) * es[1];  // r0, n1
        float u2 = (dA[2] + dBc[2] + dC[2] + dD[2]) * es[2];  // r1, n0
        float u3 = (dA[3] + dBc[3] + dC[3] + dD[3]) * es[3];  // r1, n1
        if (mw != 0xFFu) {
            if (!((mw >> n0) & 1u)) { u0 = Sv0; u2 = Sv0; }
            if (!((mw >> n1) & 1u)) { u1 = Sv1; u3 = Sv1; }
        }
        {
            uint32_t w0, w1;
            asm volatile("cvt.rn.bf16x2.f32 %0, %1, %2;" : "=r"(w0) : "f"(u2), "f"(u0));
            asm volatile("cvt.rn.bf16x2.f32 %0, %1, %2;" : "=r"(w1) : "f"(u3), "f"(u1));
            asm volatile("st.shared.b32 [%0], %1;"
                         :: "r"(nxtb + (uint32_t)(n0 * RSB) + stoff), "r"(w0));
            asm volatile("st.shared.b32 [%0], %1;"
                         :: "r"(nxtb + (uint32_t)(n1 * RSB) + stoff), "r"(w1));
        }
        if (tid < 4) {  // warp0 gidr==0: r0 == state 0
            mslotF[(cur ^ 1u) * 8 + n0] = u0;
            mslotF[(cur ^ 1u) * 8 + n1] = u1;
        }
        __syncthreads();
        cur ^= 1u;
    }

    // epilogue: den[b] = C0 + ksum*ln2 + log(sum ea * exp(trans[STOP,.]))
    {
        if (tid < 4) { kssm[n0] = ksum0; kssm[n1] = ksum1; }
        if (wid < 8) {
            int st = permf(tid);
            float ets = __expf(trans[STOP_TAG * NS + st]);
            const uint32_t bufb = smem_base + SM_EA + cur * EABUF;
            float v[NB];
#pragma unroll
            for (int n = 0; n < NB; n++) {
                uint32_t hv;
                uint32_t ad = bufb + (uint32_t)(n * RSB + tid * 2);
                asm volatile("ld.shared.u16 %0,[%1];" : "=r"(hv) : "r"(ad));
                v[n] = __uint_as_float(hv << 16) * ets;
            }
#pragma unroll
            for (int n = 0; n < NB; n++) {
                float s = v[n];
#pragma unroll
                for (int o = 16; o; o >>= 1) s += __shfl_xor_sync(~0u, s, o);
                if (lane == 0) redsm[wid * 8 + n] = s;
            }
        }
        __syncthreads();
        if (tid < 8) {
            float s = 0.f;
#pragma unroll
            for (int w = 0; w < 8; w++) s += redsm[w * 8 + tid];
            g_den[bb + tid] = C0sm[tid] + (float)kssm[tid] * LN2F + __logf(s);
        }
    }
}

// ---------------------------------------------------------------------------
// Numerator: 1 warp per batch
// ---------------------------------------------------------------------------
__global__ void num_kernel(const float* __restrict__ inputs,
                           const float* __restrict__ trans,
                           const int* __restrict__ tags,
                           const int* __restrict__ mask)
{
    int b = blockIdx.x;
    int lane = threadIdx.x;
    const int* tg = tags + b * TT;
    const int* mk = mask + b * TT;
    float sc = 0.f;
    int mc = 0;
    for (int t = lane; t < TT; t += 32) {
        int tgt = tg[t];
        int m = mk[t];
        mc += m;
        if (t >= 1) sc += trans[tgt * NS + tg[t - 1]] * (float)m;
        if (t < TT - 1) sc += inputs[((size_t)b * TT + t) * NS + tgt] * (float)m;
    }
#pragma unroll
    for (int o = 16; o; o >>= 1) {
        sc += __shfl_xor_sync(0xffffffffu, sc, o);
        mc += __shfl_xor_sync(0xffffffffu, mc, o);
    }
    if (lane == 0) {
        sc += trans[tg[0] * NS + START_TAG];
        int li = mc - 1;
        if (li < 0) li = 0;
        int lt = tg[li];
        sc += trans[STOP_TAG * NS + lt]
            + inputs[((size_t)b * TT + (TT - 1)) * NS + lt] * (float)mk[TT - 1];
        g_num[b] = sc;
    }
}

// ---------------------------------------------------------------------------
// Final reduce: sum_b (num - den)
// ---------------------------------------------------------------------------
__global__ void final_kernel(float* __restrict__ out)
{
    __shared__ float red[8];
    int tid = threadIdx.x;
    int lane = tid & 31, wid = tid >> 5;
    float v = g_num[tid] - g_den[tid];
#pragma unroll
    for (int o = 16; o; o >>= 1) v += __shfl_xor_sync(0xffffffffu, v, o);
    if (lane == 0) red[wid] = v;
    __syncthreads();
    if (tid == 0) {
        float s = 0.f;
#pragma unroll
        for (int w = 0; w < 8; w++) s += red[w];
        out[0] = s;
    }
}

extern "C" void kernel_launch(void* const* d_in, const int* in_sizes, int n_in,
                              void* d_out, int out_size)
{
    const float* inputs = (const float*)d_in[0];
    const float* trans  = (const float*)d_in[1];
    const int*   tags   = (const int*)d_in[2];
    const int*   mask   = (const int*)d_in[3];

    prep_kernel<<<256, 256>>>(trans);
    forward_kernel<<<NCTA, 512>>>(inputs, trans, mask);
    num_kernel<<<BB, 32>>>(inputs, trans, tags, mask);
    final_kernel<<<1, 256>>>((float*)d_out);
}